// round 12
// baseline (speedup 1.0000x reference)
#include <cuda_runtime.h>
#include <cuda_bf16.h>
#include <math.h>
#include <stdint.h>

// Shapes (fixed)
#define BB 32
#define TT 512
#define AA 64
#define DD 128
#define HH 256
#define MM (BB*TT)     // 16384
#define NN (DD*DD)     // 16384
#define KK HH          // 256
#define KP 512         // packed cols/row: per 32-k tile, [hi 32 | lo 32]

// Device scratch (allocation-free rule)
__device__ __align__(128) __nv_bfloat16 g_A2[(size_t)MM * KP];    // 16.7 MB
__device__ __align__(128) __nv_bfloat16 g_B2T[(size_t)NN * KP];   // 16.7 MB
__device__ __align__(128) float g_trans[(size_t)MM * NN];         // 1.07 GB

// ---------------------------------------------------------------------------
// PTX helpers (sm_80-class only — harness ptxas targets base sm_103)
// ---------------------------------------------------------------------------
__device__ __forceinline__ uint32_t smem_u32(const void* p) {
    uint32_t a;
    asm("{ .reg .u64 t; cvta.to.shared.u64 t, %1; cvt.u32.u64 %0, t; }" : "=r"(a) : "l"(p));
    return a;
}
__device__ __forceinline__ void cp16(uint32_t dst, const void* src) {
    asm volatile("cp.async.cg.shared.global [%0], [%1], 16;" :: "r"(dst), "l"(src) : "memory");
}
__device__ __forceinline__ void cp_commit() {
    asm volatile("cp.async.commit_group;" ::: "memory");
}
template <int N>
__device__ __forceinline__ void cp_wait() {
    asm volatile("cp.async.wait_group %0;" :: "n"(N) : "memory");
}
__device__ __forceinline__ void ldsm4(uint32_t* r, uint32_t addr) {
    asm volatile("ldmatrix.sync.aligned.m8n8.x4.shared.b16 {%0,%1,%2,%3}, [%4];"
                 : "=r"(r[0]), "=r"(r[1]), "=r"(r[2]), "=r"(r[3]) : "r"(addr));
}
__device__ __forceinline__ void mma_bf16(float* d, const uint32_t* a, const uint32_t* b) {
    asm volatile(
        "mma.sync.aligned.m16n8k16.row.col.f32.bf16.bf16.f32 "
        "{%0,%1,%2,%3}, {%4,%5,%6,%7}, {%8,%9}, {%0,%1,%2,%3};"
        : "+f"(d[0]), "+f"(d[1]), "+f"(d[2]), "+f"(d[3])
        : "r"(a[0]), "r"(a[1]), "r"(a[2]), "r"(a[3]), "r"(b[0]), "r"(b[1]));
}
// SW128 swizzle, closed form for row*128+kb (kb < 128)
__device__ __forceinline__ uint32_t swoff(uint32_t row, uint32_t kb) {
    return row * 128u + (kb ^ ((row & 7u) << 4));
}

// ---------------------------------------------------------------------------
// Kernel 1: h = relu(actions@w1+b1); write A2 packed [hi|lo] per 32-k tile
// ---------------------------------------------------------------------------
__global__ __launch_bounds__(256) void mlp1_kernel(const float* __restrict__ actions,
                                                   const float* __restrict__ w1,
                                                   const float* __restrict__ b1)
{
    __shared__ float as[8][AA];
    const int tid = threadIdx.x;
    const int m0 = blockIdx.x * 8;

    for (int i = tid; i < 8 * AA; i += 256)
        as[i >> 6][i & 63] = actions[(size_t)m0 * AA + i];
    __syncthreads();

    const int n = tid;                    // k index in [0,256)
    float bv = b1[n];
    float acc[8];
#pragma unroll
    for (int r = 0; r < 8; r++) acc[r] = bv;
#pragma unroll 8
    for (int a = 0; a < AA; a++) {
        float w = w1[(size_t)a * HH + n];
#pragma unroll
        for (int r = 0; r < 8; r++) acc[r] = fmaf(as[r][a], w, acc[r]);
    }
    const int koff = (n >> 5) * 64 + (n & 31);   // packed column of hi
#pragma unroll
    for (int r = 0; r < 8; r++) {
        float v = fmaxf(acc[r], 0.0f);
        __nv_bfloat16 hi = __float2bfloat16_rn(v);
        __nv_bfloat16 lo = __float2bfloat16_rn(v - __bfloat162float(hi));
        size_t row = (size_t)(m0 + r) * KP;
        g_A2[row + koff] = hi;
        g_A2[row + koff + 32] = lo;
    }
}

// ---------------------------------------------------------------------------
// Kernel 1b: B2T[n] packed [hi|lo] per 32-k tile (transpose of w2)
// ---------------------------------------------------------------------------
__global__ __launch_bounds__(256) void bprep_kernel(const float* __restrict__ w2)
{
    __shared__ float tile[32][33];
    const int tx = threadIdx.x;          // 0..31
    const int ty = threadIdx.y;          // 0..7
    const int n0 = blockIdx.x * 32;
    const int k0 = blockIdx.y * 32;
#pragma unroll
    for (int i = 0; i < 4; i++) {
        int k = k0 + ty + i * 8;
        tile[ty + i * 8][tx] = w2[(size_t)k * NN + n0 + tx];
    }
    __syncthreads();
    const int k = k0 + tx;
    const int koff = (k >> 5) * 64 + (k & 31);
#pragma unroll
    for (int i = 0; i < 4; i++) {
        int nrow = ty + i * 8;
        float v = tile[tx][nrow];        // w2[k, n0+nrow]
        __nv_bfloat16 hi = __float2bfloat16_rn(v);
        __nv_bfloat16 lo = __float2bfloat16_rn(v - __bfloat162float(hi));
        size_t row = (size_t)(n0 + nrow) * KP + koff;
        g_B2T[row] = hi;
        g_B2T[row + 32] = lo;
    }
}

// ---------------------------------------------------------------------------
// Kernel 2: bf16 mma.sync GEMM with shared-hi operand reuse (R10, measured).
// BM=BN=128, NKT=8, 3-stage cp.async, 256 threads, 2 CTAs/SM.
// ---------------------------------------------------------------------------
#define BMG 128
#define BNG 128
#define NKT 8            // 256 real k / 32 per tile
#define NSTG 3
#define A_BYTES (BMG*128)    // 16384
#define B_BYTES (BNG*128)    // 16384
#define STAGE_BYTES (A_BYTES + B_BYTES)  // 32768
#define ROWB (KP*2)          // 1024 bytes per packed row

__global__ __launch_bounds__(256, 2) void gemm8_kernel(const float* __restrict__ bias)
{
    extern __shared__ char dsm[];
    __shared__ float bias_s[BNG];

    const uint32_t dyn = smem_u32(dsm);
    const int tid = threadIdx.x;
    const int wid = tid >> 5;
    const int lane = tid & 31;
    const int m0 = blockIdx.y * BMG;
    const int n0 = blockIdx.x * BNG;

    if (tid < BNG) bias_s[tid] = bias[n0 + tid];

    const char* Abase = (const char*)g_A2;
    const char* Bbase = (const char*)g_B2T;

    auto load_stage = [&](int s, int kt) {
        uint32_t sb = dyn + s * STAGE_BYTES;
        size_t kbyte = (size_t)kt * 128;         // 128 B per packed k-tile
#pragma unroll
        for (int i = 0; i < 4; i++) {            // A: 1024 chunks of 16B
            int q = i * 256 + tid;
            uint32_t r = q >> 3, c = (q & 7) * 16;
            cp16(sb + swoff(r, c),
                 Abase + (size_t)(m0 + r) * ROWB + kbyte + c);
        }
#pragma unroll
        for (int i = 0; i < 4; i++) {            // B: 1024 chunks
            int q = i * 256 + tid;
            uint32_t r = q >> 3, c = (q & 7) * 16;
            cp16(sb + A_BYTES + swoff(r, c),
                 Bbase + (size_t)(n0 + r) * ROWB + kbyte + c);
        }
        cp_commit();
    };

    load_stage(0, 0);
    load_stage(1, 1);

    const int m_w = (wid >> 2) * 64;
    const int n_w = (wid & 3) * 32;

    const uint32_t a_row = m_w + (lane & 7) + (lane & 8);
    const uint32_t a_hk  = (lane >> 4) << 4;
    const uint32_t b_row = n_w + (lane & 7) + ((lane >> 4) << 3);
    const uint32_t b_hk  = (lane & 8) << 1;

    float acc[4][4][4];
#pragma unroll
    for (int mi = 0; mi < 4; mi++)
#pragma unroll
        for (int nt = 0; nt < 4; nt++)
#pragma unroll
            for (int e = 0; e < 4; e++) acc[mi][nt][e] = 0.0f;

#pragma unroll 1
    for (int kt = 0; kt < NKT; kt++) {
        const int s = kt % NSTG;

        if (kt + 1 < NKT) cp_wait<1>();
        else              cp_wait<0>();
        __syncthreads();

        if (kt + 2 < NKT) load_stage((kt + 2) % NSTG, kt + 2);

        const uint32_t abase = dyn + s * STAGE_BYTES;
        const uint32_t bbase = abase + A_BYTES;

#pragma unroll
        for (int ks = 0; ks < 2; ks++) {
            const uint32_t akb_h = ks * 32 + a_hk;
            const uint32_t bkb_h = ks * 32 + b_hk;
            uint32_t ah[4][4], bh[2][4];
#pragma unroll
            for (int mi = 0; mi < 4; mi++)
                ldsm4(ah[mi], abase + swoff(a_row + mi * 16, akb_h));
#pragma unroll
            for (int nj = 0; nj < 2; nj++)
                ldsm4(bh[nj], bbase + swoff(b_row + nj * 16, bkb_h));
#pragma unroll
            for (int mi = 0; mi < 4; mi++)
#pragma unroll
                for (int nj = 0; nj < 2; nj++) {
                    mma_bf16(acc[mi][2 * nj],     ah[mi], &bh[nj][0]);
                    mma_bf16(acc[mi][2 * nj + 1], ah[mi], &bh[nj][2]);
                }
            {
                uint32_t bl[2][4];
#pragma unroll
                for (int nj = 0; nj < 2; nj++)
                    ldsm4(bl[nj], bbase + swoff(b_row + nj * 16, 64 + bkb_h));
#pragma unroll
                for (int mi = 0; mi < 4; mi++)
#pragma unroll
                    for (int nj = 0; nj < 2; nj++) {
                        mma_bf16(acc[mi][2 * nj],     ah[mi], &bl[nj][0]);
                        mma_bf16(acc[mi][2 * nj + 1], ah[mi], &bl[nj][2]);
                    }
            }
#pragma unroll
            for (int mi = 0; mi < 4; mi++)
                ldsm4(ah[mi], abase + swoff(a_row + mi * 16, 64 + akb_h));
#pragma unroll
            for (int mi = 0; mi < 4; mi++)
#pragma unroll
                for (int nj = 0; nj < 2; nj++) {
                    mma_bf16(acc[mi][2 * nj],     ah[mi], &bh[nj][0]);
                    mma_bf16(acc[mi][2 * nj + 1], ah[mi], &bh[nj][2]);
                }
        }
    }

    const int cl = 2 * (lane & 3);
    const int rl = lane >> 2;
#pragma unroll
    for (int mi = 0; mi < 4; mi++) {
        int row0 = m0 + m_w + mi * 16 + rl;
#pragma unroll
        for (int nt = 0; nt < 4; nt++) {
            int lc = n_w + nt * 8 + cl;
            int col = n0 + lc;
            float bx = bias_s[lc], by = bias_s[lc + 1];
            float2 v0 = {acc[mi][nt][0] + bx, acc[mi][nt][1] + by};
            float2 v1 = {acc[mi][nt][2] + bx, acc[mi][nt][3] + by};
            *(float2*)(g_trans + (size_t)row0 * NN + col) = v0;
            *(float2*)(g_trans + (size_t)(row0 + 8) * NN + col) = v1;
        }
    }
}

// ---------------------------------------------------------------------------
// Kernel 3: scan, ONE barrier per step, LAG-1 norm (stable).
// Warp w holds state rows [8w,8w+8) in registers. Phase 1: matvec into
// red[t&1], prefetch T(t+1) (unroll-by-2 buffers, zero copies). Barrier.
// Phase 2: warp reconstructs its 8 v-values (4 LDS + 2 shfl); warps 12-15
// ALSO compute ||v_t||^2 directly from red (16 LDS/lane, conflict-free) into
// wsum[t&1]; out[t-1] emitted with exact norm rsqrt(wsum[(t-1)&1]); state
// carries v_t * inv(||v_{t-1}||) — log-dynamics rho_{t+1}=rho_t-rho_{t-1}+g,
// roots on unit circle (bounded; same class as the R8 measured-good scheme).
// Output normalization is exact (positive homogeneity).
// ---------------------------------------------------------------------------
#define RPAD 132

__global__ __launch_bounds__(512, 1) void scan_kernel(const float* __restrict__ init_s,
                                                      float* __restrict__ out)
{
    __shared__ float red[2][16 * RPAD];
    __shared__ float shist[2][DD];
    __shared__ float wsum[2][4];

    const int tid = threadIdx.x;
    const int w = tid >> 5;
    const int l = tid & 31;
    const int b = blockIdx.x;
    const float* Tb = g_trans + (size_t)b * TT * (size_t)NN;

    // init state slice (raw init_s; scale-invariant)
    float x0 = (l < 8) ? init_s[8 * w + l] : 0.0f;
    float sreg[8];
#pragma unroll
    for (int k = 0; k < 8; k++) sreg[k] = __shfl_sync(0xffffffffu, x0, k);

    // preload T(0)
    float4 TA[8], TB[8];
#pragma unroll
    for (int ii = 0; ii < 8; ii++)
        TA[ii] = *(const float4*)(Tb + (size_t)(8 * w + ii) * DD + 4 * l);

    const int vii = l >> 2;          // which of my warp's 8 values
    const int q = l & 3;             // quarter of the 16-partial tree
    const int jj = 8 * w + vii;

    auto step = [&](float4 (&cur)[8], float4 (&nx)[8], int t) {
        // ---- phase 1 ----
        if (t + 1 < TT) {
            const float* Tn = Tb + (size_t)(t + 1) * NN;
#pragma unroll
            for (int ii = 0; ii < 8; ii++)
                nx[ii] = *(const float4*)(Tn + (size_t)(8 * w + ii) * DD + 4 * l);
        }
        float4 p = {0.0f, 0.0f, 0.0f, 0.0f};
#pragma unroll
        for (int ii = 0; ii < 8; ii++) {
            p.x = fmaf(sreg[ii], cur[ii].x, p.x);
            p.y = fmaf(sreg[ii], cur[ii].y, p.y);
            p.z = fmaf(sreg[ii], cur[ii].z, p.z);
            p.w = fmaf(sreg[ii], cur[ii].w, p.w);
        }
        *(float4*)&red[t & 1][w * RPAD + 4 * l] = p;
        __syncthreads();             // the ONE barrier

        // ---- phase 2 ----
        const float* rb = &red[t & 1][0];
        float part = rb[(4 * q + 0) * RPAD + jj] + rb[(4 * q + 1) * RPAD + jj]
                   + rb[(4 * q + 2) * RPAD + jj] + rb[(4 * q + 3) * RPAD + jj];
        part += __shfl_xor_sync(0xffffffffu, part, 1);
        part += __shfl_xor_sync(0xffffffffu, part, 2);
        float v = fmaxf(part, 0.0f); // all 4 lanes of the group hold v_jj

        // norm duty: warps 12-15 compute ||v_t||^2 directly from red
        if (w >= 12) {
            const int k = w - 12;
            const int col = k * 32 + l;
            float s = 0.0f;
#pragma unroll
            for (int ch = 0; ch < 16; ch++) s += rb[ch * RPAD + col];
            s = fmaxf(s, 0.0f);
            float sq = s * s;
#pragma unroll
            for (int o = 16; o; o >>= 1) sq += __shfl_xor_sync(0xffffffffu, sq, o);
            if (l == 0) wsum[t & 1][k] = sq;
        }

        if (q == 0) shist[t & 1][jj] = v;

        float inv = 1.0f;
        if (t >= 1) {
            const float* ws = wsum[(t - 1) & 1];
            inv = rsqrtf(fmaxf((ws[0] + ws[1]) + (ws[2] + ws[3]), 1e-24f));
            if (tid < DD)            // out[t-1] with its exact norm
                out[((size_t)b * TT + (t - 1)) * DD + tid] = shist[(t - 1) & 1][tid] * inv;
        }
#pragma unroll
        for (int k = 0; k < 8; k++)
            sreg[k] = __shfl_sync(0xffffffffu, v, 4 * k) * inv;
    };

#pragma unroll 1
    for (int t = 0; t < TT; t += 2) {
        step(TA, TB, t);
        step(TB, TA, t + 1);
    }

    // drain: out[TT-1] (wsum[(TT-1)&1] computed during step TT-1)
    __syncthreads();
    if (tid < DD) {
        const float* ws = wsum[(TT - 1) & 1];
        float inv = rsqrtf(fmaxf((ws[0] + ws[1]) + (ws[2] + ws[3]), 1e-24f));
        out[((size_t)b * TT + (TT - 1)) * DD + tid] = shist[(TT - 1) & 1][tid] * inv;
    }
}

// ---------------------------------------------------------------------------
extern "C" void kernel_launch(void* const* d_in, const int* in_sizes, int n_in,
                              void* d_out, int out_size)
{
    const float* actions = (const float*)d_in[0];
    const float* init_s  = (const float*)d_in[1];
    const float* w1      = (const float*)d_in[2];
    const float* b1      = (const float*)d_in[3];
    const float* w2      = (const float*)d_in[4];
    const float* b2      = (const float*)d_in[5];
    float* out = (float*)d_out;

    cudaFuncSetAttribute(gemm8_kernel, cudaFuncAttributeMaxDynamicSharedMemorySize,
                         NSTG * STAGE_BYTES);

    mlp1_kernel<<<MM / 8, 256>>>(actions, w1, b1);
    bprep_kernel<<<dim3(NN / 32, KK / 32), dim3(32, 8)>>>(w2);
    gemm8_kernel<<<dim3(NN / BNG, MM / BMG), 256, NSTG * STAGE_BYTES>>>(b2);
    scan_kernel<<<BB, 512>>>(init_s, out);
}

// round 13
// speedup vs baseline: 1.1633x; 1.1633x over previous
#include <cuda_runtime.h>
#include <cuda_bf16.h>
#include <math.h>
#include <stdint.h>

// Shapes (fixed)
#define BB 32
#define TT 512
#define AA 64
#define DD 128
#define HH 256
#define MM (BB*TT)     // 16384
#define NN (DD*DD)     // 16384
#define KK HH          // 256
#define KP 512         // packed cols/row: per 32-k tile, [hi 32 | lo 32]

// Device scratch (allocation-free rule)
__device__ __align__(128) __nv_bfloat16 g_A2[(size_t)MM * KP];    // 16.7 MB
__device__ __align__(128) __nv_bfloat16 g_B2T[(size_t)NN * KP];   // 16.7 MB
__device__ __align__(128) float g_trans[(size_t)MM * NN];         // 1.07 GB
__device__ float g_state[BB][DD];                                 // scan handoff

// ---------------------------------------------------------------------------
// PTX helpers (sm_80-class only — harness ptxas targets base sm_103)
// ---------------------------------------------------------------------------
__device__ __forceinline__ uint32_t smem_u32(const void* p) {
    uint32_t a;
    asm("{ .reg .u64 t; cvta.to.shared.u64 t, %1; cvt.u32.u64 %0, t; }" : "=r"(a) : "l"(p));
    return a;
}
__device__ __forceinline__ void cp16(uint32_t dst, const void* src) {
    asm volatile("cp.async.cg.shared.global [%0], [%1], 16;" :: "r"(dst), "l"(src) : "memory");
}
__device__ __forceinline__ void cp_commit() {
    asm volatile("cp.async.commit_group;" ::: "memory");
}
template <int N>
__device__ __forceinline__ void cp_wait() {
    asm volatile("cp.async.wait_group %0;" :: "n"(N) : "memory");
}
__device__ __forceinline__ void ldsm4(uint32_t* r, uint32_t addr) {
    asm volatile("ldmatrix.sync.aligned.m8n8.x4.shared.b16 {%0,%1,%2,%3}, [%4];"
                 : "=r"(r[0]), "=r"(r[1]), "=r"(r[2]), "=r"(r[3]) : "r"(addr));
}
__device__ __forceinline__ void mma_bf16(float* d, const uint32_t* a, const uint32_t* b) {
    asm volatile(
        "mma.sync.aligned.m16n8k16.row.col.f32.bf16.bf16.f32 "
        "{%0,%1,%2,%3}, {%4,%5,%6,%7}, {%8,%9}, {%0,%1,%2,%3};"
        : "+f"(d[0]), "+f"(d[1]), "+f"(d[2]), "+f"(d[3])
        : "r"(a[0]), "r"(a[1]), "r"(a[2]), "r"(a[3]), "r"(b[0]), "r"(b[1]));
}
// SW128 swizzle, closed form for row*128+kb (kb < 128)
__device__ __forceinline__ uint32_t swoff(uint32_t row, uint32_t kb) {
    return row * 128u + (kb ^ ((row & 7u) << 4));
}

// ---------------------------------------------------------------------------
// Kernel 1: h = relu(actions@w1+b1); write A2 packed [hi|lo] per 32-k tile
// ---------------------------------------------------------------------------
__global__ __launch_bounds__(256) void mlp1_kernel(const float* __restrict__ actions,
                                                   const float* __restrict__ w1,
                                                   const float* __restrict__ b1)
{
    __shared__ float as[8][AA];
    const int tid = threadIdx.x;
    const int m0 = blockIdx.x * 8;

    for (int i = tid; i < 8 * AA; i += 256)
        as[i >> 6][i & 63] = actions[(size_t)m0 * AA + i];
    __syncthreads();

    const int n = tid;                    // k index in [0,256)
    float bv = b1[n];
    float acc[8];
#pragma unroll
    for (int r = 0; r < 8; r++) acc[r] = bv;
#pragma unroll 8
    for (int a = 0; a < AA; a++) {
        float w = w1[(size_t)a * HH + n];
#pragma unroll
        for (int r = 0; r < 8; r++) acc[r] = fmaf(as[r][a], w, acc[r]);
    }
    const int koff = (n >> 5) * 64 + (n & 31);   // packed column of hi
#pragma unroll
    for (int r = 0; r < 8; r++) {
        float v = fmaxf(acc[r], 0.0f);
        __nv_bfloat16 hi = __float2bfloat16_rn(v);
        __nv_bfloat16 lo = __float2bfloat16_rn(v - __bfloat162float(hi));
        size_t row = (size_t)(m0 + r) * KP;
        g_A2[row + koff] = hi;
        g_A2[row + koff + 32] = lo;
    }
}

// ---------------------------------------------------------------------------
// Kernel 1b: B2T[n] packed [hi|lo] per 32-k tile (transpose of w2)
// ---------------------------------------------------------------------------
__global__ __launch_bounds__(256) void bprep_kernel(const float* __restrict__ w2)
{
    __shared__ float tile[32][33];
    const int tx = threadIdx.x;          // 0..31
    const int ty = threadIdx.y;          // 0..7
    const int n0 = blockIdx.x * 32;
    const int k0 = blockIdx.y * 32;
#pragma unroll
    for (int i = 0; i < 4; i++) {
        int k = k0 + ty + i * 8;
        tile[ty + i * 8][tx] = w2[(size_t)k * NN + n0 + tx];
    }
    __syncthreads();
    const int k = k0 + tx;
    const int koff = (k >> 5) * 64 + (k & 31);
#pragma unroll
    for (int i = 0; i < 4; i++) {
        int nrow = ty + i * 8;
        float v = tile[tx][nrow];        // w2[k, n0+nrow]
        __nv_bfloat16 hi = __float2bfloat16_rn(v);
        __nv_bfloat16 lo = __float2bfloat16_rn(v - __bfloat162float(hi));
        size_t row = (size_t)(n0 + nrow) * KP + koff;
        g_B2T[row] = hi;
        g_B2T[row + 32] = hi, g_B2T[row + 32] = lo;
    }
}

// ---------------------------------------------------------------------------
// Kernel 2: bf16 mma.sync GEMM with shared-hi operand reuse (R10, measured).
// y-index remapped t-chunk-major: ylin in [0,128), tc=ylin>>5, bb=ylin&31,
// m0 = (bb*4+tc)*128  →  y-range [0,96) covers t in [0,384) for all batches.
// ---------------------------------------------------------------------------
#define BMG 128
#define BNG 128
#define NKT 8            // 256 real k / 32 per tile
#define NSTG 3
#define A_BYTES (BMG*128)    // 16384
#define B_BYTES (BNG*128)    // 16384
#define STAGE_BYTES (A_BYTES + B_BYTES)  // 32768
#define ROWB (KP*2)          // 1024 bytes per packed row

__global__ __launch_bounds__(256, 2) void gemm8_kernel(const float* __restrict__ bias,
                                                       int yoff)
{
    extern __shared__ char dsm[];
    __shared__ float bias_s[BNG];

    const uint32_t dyn = smem_u32(dsm);
    const int tid = threadIdx.x;
    const int wid = tid >> 5;
    const int lane = tid & 31;
    const int ylin = blockIdx.y + yoff;
    const int m0 = ((ylin & 31) * 4 + (ylin >> 5)) * BMG;
    const int n0 = blockIdx.x * BNG;

    if (tid < BNG) bias_s[tid] = bias[n0 + tid];

    const char* Abase = (const char*)g_A2;
    const char* Bbase = (const char*)g_B2T;

    auto load_stage = [&](int s, int kt) {
        uint32_t sb = dyn + s * STAGE_BYTES;
        size_t kbyte = (size_t)kt * 128;         // 128 B per packed k-tile
#pragma unroll
        for (int i = 0; i < 4; i++) {            // A: 1024 chunks of 16B
            int q = i * 256 + tid;
            uint32_t r = q >> 3, c = (q & 7) * 16;
            cp16(sb + swoff(r, c),
                 Abase + (size_t)(m0 + r) * ROWB + kbyte + c);
        }
#pragma unroll
        for (int i = 0; i < 4; i++) {            // B: 1024 chunks
            int q = i * 256 + tid;
            uint32_t r = q >> 3, c = (q & 7) * 16;
            cp16(sb + A_BYTES + swoff(r, c),
                 Bbase + (size_t)(n0 + r) * ROWB + kbyte + c);
        }
        cp_commit();
    };

    load_stage(0, 0);
    load_stage(1, 1);

    const int m_w = (wid >> 2) * 64;
    const int n_w = (wid & 3) * 32;

    const uint32_t a_row = m_w + (lane & 7) + (lane & 8);
    const uint32_t a_hk  = (lane >> 4) << 4;
    const uint32_t b_row = n_w + (lane & 7) + ((lane >> 4) << 3);
    const uint32_t b_hk  = (lane & 8) << 1;

    float acc[4][4][4];
#pragma unroll
    for (int mi = 0; mi < 4; mi++)
#pragma unroll
        for (int nt = 0; nt < 4; nt++)
#pragma unroll
            for (int e = 0; e < 4; e++) acc[mi][nt][e] = 0.0f;

#pragma unroll 1
    for (int kt = 0; kt < NKT; kt++) {
        const int s = kt % NSTG;

        if (kt + 1 < NKT) cp_wait<1>();
        else              cp_wait<0>();
        __syncthreads();

        if (kt + 2 < NKT) load_stage((kt + 2) % NSTG, kt + 2);

        const uint32_t abase = dyn + s * STAGE_BYTES;
        const uint32_t bbase = abase + A_BYTES;

#pragma unroll
        for (int ks = 0; ks < 2; ks++) {
            const uint32_t akb_h = ks * 32 + a_hk;
            const uint32_t bkb_h = ks * 32 + b_hk;
            uint32_t ah[4][4], bh[2][4];
#pragma unroll
            for (int mi = 0; mi < 4; mi++)
                ldsm4(ah[mi], abase + swoff(a_row + mi * 16, akb_h));
#pragma unroll
            for (int nj = 0; nj < 2; nj++)
                ldsm4(bh[nj], bbase + swoff(b_row + nj * 16, bkb_h));
#pragma unroll
            for (int mi = 0; mi < 4; mi++)
#pragma unroll
                for (int nj = 0; nj < 2; nj++) {
                    mma_bf16(acc[mi][2 * nj],     ah[mi], &bh[nj][0]);
                    mma_bf16(acc[mi][2 * nj + 1], ah[mi], &bh[nj][2]);
                }
            {
                uint32_t bl[2][4];
#pragma unroll
                for (int nj = 0; nj < 2; nj++)
                    ldsm4(bl[nj], bbase + swoff(b_row + nj * 16, 64 + bkb_h));
#pragma unroll
                for (int mi = 0; mi < 4; mi++)
#pragma unroll
                    for (int nj = 0; nj < 2; nj++) {
                        mma_bf16(acc[mi][2 * nj],     ah[mi], &bl[nj][0]);
                        mma_bf16(acc[mi][2 * nj + 1], ah[mi], &bl[nj][2]);
                    }
            }
#pragma unroll
            for (int mi = 0; mi < 4; mi++)
                ldsm4(ah[mi], abase + swoff(a_row + mi * 16, 64 + akb_h));
#pragma unroll
            for (int mi = 0; mi < 4; mi++)
#pragma unroll
                for (int nj = 0; nj < 2; nj++) {
                    mma_bf16(acc[mi][2 * nj],     ah[mi], &bh[nj][0]);
                    mma_bf16(acc[mi][2 * nj + 1], ah[mi], &bh[nj][2]);
                }
        }
    }

    const int cl = 2 * (lane & 3);
    const int rl = lane >> 2;
#pragma unroll
    for (int mi = 0; mi < 4; mi++) {
        int row0 = m0 + m_w + mi * 16 + rl;
#pragma unroll
        for (int nt = 0; nt < 4; nt++) {
            int lc = n_w + nt * 8 + cl;
            int col = n0 + lc;
            float bx = bias_s[lc], by = bias_s[lc + 1];
            float2 v0 = {acc[mi][nt][0] + bx, acc[mi][nt][1] + by};
            float2 v1 = {acc[mi][nt][2] + bx, acc[mi][nt][3] + by};
            *(float2*)(g_trans + (size_t)row0 * NN + col) = v0;
            *(float2*)(g_trans + (size_t)(row0 + 8) * NN + col) = v1;
        }
    }
}

// ---------------------------------------------------------------------------
// Scan step core (R8/R10 measured structure): double-buffered state; warps
// 12-15 compute state norm during matvec; 2 barriers/step; distance-1
// register prefetch. Parameterized over [t0, t1) with prefetch clamp.
// ---------------------------------------------------------------------------
template <int T0, int T1>
__device__ __forceinline__ void scan_range(const float* __restrict__ Tb, int b,
                                           float* __restrict__ out,
                                           float (*s_nx)[DD], float (*red)[DD],
                                           float* wsum)
{
    const int tid = threadIdx.x;
    const int w = tid >> 5;
    const int l = tid & 31;
    const int c = w;                     // 8-row chunk
    const int j = l * 4;                 // 4-col group

    float4 cur[8];
#pragma unroll
    for (int ii = 0; ii < 8; ii++)
        cur[ii] = *(const float4*)(Tb + (size_t)T0 * NN + (size_t)(c * 8 + ii) * DD + j);
    __syncthreads();                     // BAR_A

#pragma unroll 1
    for (int t = T0; t < T1; t++) {
        const int rb = (t & 1) ^ 1;
        const int wb = t & 1;

        float4 nxt[8];
        if (t + 1 < T1) {
            const float* Tn = Tb + (size_t)(t + 1) * NN;
#pragma unroll
            for (int ii = 0; ii < 8; ii++)
                nxt[ii] = *(const float4*)(Tn + (size_t)(c * 8 + ii) * DD + j);
        }

        float4 p = {0.0f, 0.0f, 0.0f, 0.0f};
#pragma unroll
        for (int ii = 0; ii < 8; ii++) {
            float sv = s_nx[rb][c * 8 + ii];
            p.x = fmaf(sv, cur[ii].x, p.x);
            p.y = fmaf(sv, cur[ii].y, p.y);
            p.z = fmaf(sv, cur[ii].z, p.z);
            p.w = fmaf(sv, cur[ii].w, p.w);
        }
        *(float4*)&red[c][j] = p;

        if (w >= 12) {
            const int k = w - 12;
            float sv = s_nx[rb][k * 32 + l];
            float sq = sv * sv;
#pragma unroll
            for (int o = 16; o; o >>= 1) sq += __shfl_xor_sync(0xffffffffu, sq, o);
            if (l == 0) wsum[k] = sq;
        }
        __syncthreads();                 // BAR_B

        if (tid < DD) {
            float s0 = red[0][tid] + red[1][tid];
            float s1 = red[2][tid] + red[3][tid];
            float s2 = red[4][tid] + red[5][tid];
            float s3 = red[6][tid] + red[7][tid];
            float s4 = red[8][tid] + red[9][tid];
            float s5 = red[10][tid] + red[11][tid];
            float s6 = red[12][tid] + red[13][tid];
            float s7 = red[14][tid] + red[15][tid];
            float v = ((s0 + s1) + (s2 + s3)) + ((s4 + s5) + (s6 + s7));
            v = fmaxf(v, 0.0f);

            float inv = rsqrtf(fmaxf((wsum[0] + wsum[1]) + (wsum[2] + wsum[3]), 1e-24f));
            if (t > 0)
                out[((size_t)b * TT + (t - 1)) * DD + tid] = s_nx[rb][tid] * inv;
            s_nx[wb][tid] = v * inv;     // positive scale: exact (homogeneous)
        }
#pragma unroll
        for (int ii = 0; ii < 8; ii++) cur[ii] = nxt[ii];
        __syncthreads();                 // BAR_A (next step)
    }
}

#define TSPLIT 384

__global__ __launch_bounds__(512, 1) void scanA_kernel(const float* __restrict__ init_s,
                                                       float* __restrict__ out)
{
    __shared__ float s_nx[2][DD];
    __shared__ float red[16][DD];
    __shared__ float wsum[4];

    const int tid = threadIdx.x;
    const int b = blockIdx.x;
    const float* Tb = g_trans + (size_t)b * TT * (size_t)NN;

    if (tid < DD) s_nx[1][tid] = init_s[tid];   // rb of t=0

    scan_range<0, TSPLIT>(Tb, b, out, s_nx, red, wsum);

    // handoff: state for step TSPLIT is s_nx[1] (wb of t=TSPLIT-1=383)
    if (tid < DD) g_state[b][tid] = s_nx[(TSPLIT - 1) & 1][tid];
}

__global__ __launch_bounds__(512, 1) void scanB_kernel(float* __restrict__ out)
{
    __shared__ float s_nx[2][DD];
    __shared__ float red[16][DD];
    __shared__ float wsum[4];

    const int tid = threadIdx.x;
    const int w = tid >> 5;
    const int l = tid & 31;
    const int b = blockIdx.x;
    const float* Tb = g_trans + (size_t)b * TT * (size_t)NN;

    if (tid < DD) s_nx[(TSPLIT & 1) ^ 1][tid] = g_state[b][tid];

    scan_range<TSPLIT, TT>(Tb, b, out, s_nx, red, wsum);

    // drain: out[TT-1] from s_nx[(TT-1)&1]
    const int fb = (TT - 1) & 1;
    if (w >= 12) {
        const int k = w - 12;
        float sv = s_nx[fb][k * 32 + l];
        float sq = sv * sv;
#pragma unroll
        for (int o = 16; o; o >>= 1) sq += __shfl_xor_sync(0xffffffffu, sq, o);
        if (l == 0) wsum[k] = sq;
    }
    __syncthreads();
    if (tid < DD) {
        float inv = rsqrtf(fmaxf((wsum[0] + wsum[1]) + (wsum[2] + wsum[3]), 1e-24f));
        out[((size_t)b * TT + (TT - 1)) * DD + tid] = s_nx[fb][tid] * inv;
    }
}

// ---------------------------------------------------------------------------
extern "C" void kernel_launch(void* const* d_in, const int* in_sizes, int n_in,
                              void* d_out, int out_size)
{
    const float* actions = (const float*)d_in[0];
    const float* init_s  = (const float*)d_in[1];
    const float* w1      = (const float*)d_in[2];
    const float* b1      = (const float*)d_in[3];
    const float* w2      = (const float*)d_in[4];
    const float* b2      = (const float*)d_in[5];
    float* out = (float*)d_out;

    static bool s_init = false;
    static cudaStream_t s2;
    static cudaEvent_t evA, evB, evJ;
    if (!s_init) {
        cudaStreamCreateWithFlags(&s2, cudaStreamNonBlocking);
        cudaEventCreateWithFlags(&evA, cudaEventDisableTiming);
        cudaEventCreateWithFlags(&evB, cudaEventDisableTiming);
        cudaEventCreateWithFlags(&evJ, cudaEventDisableTiming);
        s_init = true;
    }

    cudaFuncSetAttribute(gemm8_kernel, cudaFuncAttributeMaxDynamicSharedMemorySize,
                         NSTG * STAGE_BYTES);

    mlp1_kernel<<<MM / 8, 256>>>(actions, w1, b1);
    bprep_kernel<<<dim3(NN / 32, KK / 32), dim3(32, 8)>>>(w2);

    // gemmA: t-chunks 0..2 (y 0..95) — all batches, t in [0,384)
    gemm8_kernel<<<dim3(NN / BNG, 96), 256, NSTG * STAGE_BYTES>>>(b2, 0);
    cudaEventRecord(evA, 0);

    // scanA on s2, concurrent with gemmB
    cudaStreamWaitEvent(s2, evA, 0);
    scanA_kernel<<<BB, 512, 0, s2>>>(init_s, out);

    // gemmB: t-chunk 3 (y 96..127) — t in [384,512)
    gemm8_kernel<<<dim3(NN / BNG, 32), 256, NSTG * STAGE_BYTES>>>(b2, 96);
    cudaEventRecord(evB, 0);

    // scanB after gemmB (and after scanA by s2 stream order)
    cudaStreamWaitEvent(s2, evB, 0);
    scanB_kernel<<<BB, 512, 0, s2>>>(out);

    // join back to the main stream
    cudaEventRecord(evJ, s2);
    cudaStreamWaitEvent(0, evJ, 0);
}

// round 16
// speedup vs baseline: 1.1818x; 1.0159x over previous
#include <cuda_runtime.h>
#include <cuda_bf16.h>
#include <math.h>
#include <stdint.h>

// Shapes (fixed)
#define BB 32
#define TT 512
#define AA 64
#define DD 128
#define HH 256
#define MM (BB*TT)     // 16384
#define NN (DD*DD)     // 16384
#define KK HH          // 256
#define KP 512         // packed cols/row: per 32-k tile, [hi 32 | lo 32]

// Device scratch (allocation-free rule)
__device__ __align__(128) __nv_bfloat16 g_A2[(size_t)MM * KP];    // 16.7 MB
__device__ __align__(128) __nv_bfloat16 g_B2T[(size_t)NN * KP];   // 16.7 MB
__device__ __align__(128) float g_trans[(size_t)MM * NN];         // 1.07 GB
__device__ float g_state[BB][DD];                                 // scan handoff

// ---------------------------------------------------------------------------
// PTX helpers (sm_80-class only — harness ptxas targets base sm_103)
// ---------------------------------------------------------------------------
__device__ __forceinline__ uint32_t smem_u32(const void* p) {
    uint32_t a;
    asm("{ .reg .u64 t; cvta.to.shared.u64 t, %1; cvt.u32.u64 %0, t; }" : "=r"(a) : "l"(p));
    return a;
}
__device__ __forceinline__ void cp16(uint32_t dst, const void* src) {
    asm volatile("cp.async.cg.shared.global [%0], [%1], 16;" :: "r"(dst), "l"(src) : "memory");
}
__device__ __forceinline__ void cp_commit() {
    asm volatile("cp.async.commit_group;" ::: "memory");
}
template <int N>
__device__ __forceinline__ void cp_wait() {
    asm volatile("cp.async.wait_group %0;" :: "n"(N) : "memory");
}
__device__ __forceinline__ void ldsm4(uint32_t* r, uint32_t addr) {
    asm volatile("ldmatrix.sync.aligned.m8n8.x4.shared.b16 {%0,%1,%2,%3}, [%4];"
                 : "=r"(r[0]), "=r"(r[1]), "=r"(r[2]), "=r"(r[3]) : "r"(addr));
}
__device__ __forceinline__ void mma_bf16(float* d, const uint32_t* a, const uint32_t* b) {
    asm volatile(
        "mma.sync.aligned.m16n8k16.row.col.f32.bf16.bf16.f32 "
        "{%0,%1,%2,%3}, {%4,%5,%6,%7}, {%8,%9}, {%0,%1,%2,%3};"
        : "+f"(d[0]), "+f"(d[1]), "+f"(d[2]), "+f"(d[3])
        : "r"(a[0]), "r"(a[1]), "r"(a[2]), "r"(a[3]), "r"(b[0]), "r"(b[1]));
}
// streaming (evict-first) float4 load — trans is read exactly once
__device__ __forceinline__ float4 ldg_cs4(const float* p) {
    float4 v;
    asm volatile("ld.global.cs.v4.f32 {%0,%1,%2,%3}, [%4];"
                 : "=f"(v.x), "=f"(v.y), "=f"(v.z), "=f"(v.w) : "l"(p));
    return v;
}
// streaming (evict-first) float2 store — trans is written exactly once
__device__ __forceinline__ void stg_cs2(float* p, float2 v) {
    asm volatile("st.global.cs.v2.f32 [%0], {%1,%2};" :: "l"(p), "f"(v.x), "f"(v.y) : "memory");
}
// SW128 swizzle, closed form for row*128+kb (kb < 128)
__device__ __forceinline__ uint32_t swoff(uint32_t row, uint32_t kb) {
    return row * 128u + (kb ^ ((row & 7u) << 4));
}

// ---------------------------------------------------------------------------
// Kernel 1: h = relu(actions@w1+b1); write A2 packed [hi|lo] per 32-k tile
// ---------------------------------------------------------------------------
__global__ __launch_bounds__(256) void mlp1_kernel(const float* __restrict__ actions,
                                                   const float* __restrict__ w1,
                                                   const float* __restrict__ b1)
{
    __shared__ float as[8][AA];
    const int tid = threadIdx.x;
    const int m0 = blockIdx.x * 8;

    for (int i = tid; i < 8 * AA; i += 256)
        as[i >> 6][i & 63] = actions[(size_t)m0 * AA + i];
    __syncthreads();

    const int n = tid;                    // k index in [0,256)
    float bv = b1[n];
    float acc[8];
#pragma unroll
    for (int r = 0; r < 8; r++) acc[r] = bv;
#pragma unroll 8
    for (int a = 0; a < AA; a++) {
        float w = w1[(size_t)a * HH + n];
#pragma unroll
        for (int r = 0; r < 8; r++) acc[r] = fmaf(as[r][a], w, acc[r]);
    }
    const int koff = (n >> 5) * 64 + (n & 31);   // packed column of hi
#pragma unroll
    for (int r = 0; r < 8; r++) {
        float v = fmaxf(acc[r], 0.0f);
        __nv_bfloat16 hi = __float2bfloat16_rn(v);
        __nv_bfloat16 lo = __float2bfloat16_rn(v - __bfloat162float(hi));
        size_t row = (size_t)(m0 + r) * KP;
        g_A2[row + koff] = hi;
        g_A2[row + koff + 32] = lo;
    }
}

// ---------------------------------------------------------------------------
// Kernel 1b: B2T[n] packed [hi|lo] per 32-k tile (transpose of w2)
// ---------------------------------------------------------------------------
__global__ __launch_bounds__(256) void bprep_kernel(const float* __restrict__ w2)
{
    __shared__ float tile[32][33];
    const int tx = threadIdx.x;          // 0..31
    const int ty = threadIdx.y;          // 0..7
    const int n0 = blockIdx.x * 32;
    const int k0 = blockIdx.y * 32;
#pragma unroll
    for (int i = 0; i < 4; i++) {
        int k = k0 + ty + i * 8;
        tile[ty + i * 8][tx] = w2[(size_t)k * NN + n0 + tx];
    }
    __syncthreads();
    const int k = k0 + tx;
    const int koff = (k >> 5) * 64 + (k & 31);
#pragma unroll
    for (int i = 0; i < 4; i++) {
        int nrow = ty + i * 8;
        float v = tile[tx][nrow];        // w2[k, n0+nrow]
        __nv_bfloat16 hi = __float2bfloat16_rn(v);
        __nv_bfloat16 lo = __float2bfloat16_rn(v - __bfloat162float(hi));
        size_t row = (size_t)(n0 + nrow) * KP + koff;
        g_B2T[row] = hi;
        g_B2T[row + 32] = lo;
    }
}

// ---------------------------------------------------------------------------
// Kernel 2: bf16 mma.sync GEMM with shared-hi operand reuse (R10, measured).
// y remapped t-chunk-major: m0 = ((ylin&31)*4 + (ylin>>5))*128.
// Epilogue stores use st.global.cs (trans written once; keep L2 for operands).
// ---------------------------------------------------------------------------
#define BMG 128
#define BNG 128
#define NKT 8            // 256 real k / 32 per tile
#define NSTG 3
#define A_BYTES (BMG*128)    // 16384
#define B_BYTES (BNG*128)    // 16384
#define STAGE_BYTES (A_BYTES + B_BYTES)  // 32768
#define ROWB (KP*2)          // 1024 bytes per packed row

__global__ __launch_bounds__(256, 2) void gemm8_kernel(const float* __restrict__ bias,
                                                       int yoff)
{
    extern __shared__ char dsm[];
    __shared__ float bias_s[BNG];

    const uint32_t dyn = smem_u32(dsm);
    const int tid = threadIdx.x;
    const int wid = tid >> 5;
    const int lane = tid & 31;
    const int ylin = blockIdx.y + yoff;
    const int m0 = ((ylin & 31) * 4 + (ylin >> 5)) * BMG;
    const int n0 = blockIdx.x * BNG;

    if (tid < BNG) bias_s[tid] = bias[n0 + tid];

    const char* Abase = (const char*)g_A2;
    const char* Bbase = (const char*)g_B2T;

    auto load_stage = [&](int s, int kt) {
        uint32_t sb = dyn + s * STAGE_BYTES;
        size_t kbyte = (size_t)kt * 128;         // 128 B per packed k-tile
#pragma unroll
        for (int i = 0; i < 4; i++) {            // A: 1024 chunks of 16B
            int q = i * 256 + tid;
            uint32_t r = q >> 3, c = (q & 7) * 16;
            cp16(sb + swoff(r, c),
                 Abase + (size_t)(m0 + r) * ROWB + kbyte + c);
        }
#pragma unroll
        for (int i = 0; i < 4; i++) {            // B: 1024 chunks
            int q = i * 256 + tid;
            uint32_t r = q >> 3, c = (q & 7) * 16;
            cp16(sb + A_BYTES + swoff(r, c),
                 Bbase + (size_t)(n0 + r) * ROWB + kbyte + c);
        }
        cp_commit();
    };

    load_stage(0, 0);
    load_stage(1, 1);

    const int m_w = (wid >> 2) * 64;
    const int n_w = (wid & 3) * 32;

    const uint32_t a_row = m_w + (lane & 7) + (lane & 8);
    const uint32_t a_hk  = (lane >> 4) << 4;
    const uint32_t b_row = n_w + (lane & 7) + ((lane >> 4) << 3);
    const uint32_t b_hk  = (lane & 8) << 1;

    float acc[4][4][4];
#pragma unroll
    for (int mi = 0; mi < 4; mi++)
#pragma unroll
        for (int nt = 0; nt < 4; nt++)
#pragma unroll
            for (int e = 0; e < 4; e++) acc[mi][nt][e] = 0.0f;

#pragma unroll 1
    for (int kt = 0; kt < NKT; kt++) {
        const int s = kt % NSTG;

        if (kt + 1 < NKT) cp_wait<1>();
        else              cp_wait<0>();
        __syncthreads();

        if (kt + 2 < NKT) load_stage((kt + 2) % NSTG, kt + 2);

        const uint32_t abase = dyn + s * STAGE_BYTES;
        const uint32_t bbase = abase + A_BYTES;

#pragma unroll
        for (int ks = 0; ks < 2; ks++) {
            const uint32_t akb_h = ks * 32 + a_hk;
            const uint32_t bkb_h = ks * 32 + b_hk;
            uint32_t ah[4][4], bh[2][4];
#pragma unroll
            for (int mi = 0; mi < 4; mi++)
                ldsm4(ah[mi], abase + swoff(a_row + mi * 16, akb_h));
#pragma unroll
            for (int nj = 0; nj < 2; nj++)
                ldsm4(bh[nj], bbase + swoff(b_row + nj * 16, bkb_h));
#pragma unroll
            for (int mi = 0; mi < 4; mi++)
#pragma unroll
                for (int nj = 0; nj < 2; nj++) {
                    mma_bf16(acc[mi][2 * nj],     ah[mi], &bh[nj][0]);
                    mma_bf16(acc[mi][2 * nj + 1], ah[mi], &bh[nj][2]);
                }
            {
                uint32_t bl[2][4];
#pragma unroll
                for (int nj = 0; nj < 2; nj++)
                    ldsm4(bl[nj], bbase + swoff(b_row + nj * 16, 64 + bkb_h));
#pragma unroll
                for (int mi = 0; mi < 4; mi++)
#pragma unroll
                    for (int nj = 0; nj < 2; nj++) {
                        mma_bf16(acc[mi][2 * nj],     ah[mi], &bl[nj][0]);
                        mma_bf16(acc[mi][2 * nj + 1], ah[mi], &bl[nj][2]);
                    }
            }
#pragma unroll
            for (int mi = 0; mi < 4; mi++)
                ldsm4(ah[mi], abase + swoff(a_row + mi * 16, 64 + akb_h));
#pragma unroll
            for (int mi = 0; mi < 4; mi++)
#pragma unroll
                for (int nj = 0; nj < 2; nj++) {
                    mma_bf16(acc[mi][2 * nj],     ah[mi], &bh[nj][0]);
                    mma_bf16(acc[mi][2 * nj + 1], ah[mi], &bh[nj][2]);
                }
        }
    }

    const int cl = 2 * (lane & 3);
    const int rl = lane >> 2;
#pragma unroll
    for (int mi = 0; mi < 4; mi++) {
        int row0 = m0 + m_w + mi * 16 + rl;
#pragma unroll
        for (int nt = 0; nt < 4; nt++) {
            int lc = n_w + nt * 8 + cl;
            int col = n0 + lc;
            float bx = bias_s[lc], by = bias_s[lc + 1];
            float2 v0 = {acc[mi][nt][0] + bx, acc[mi][nt][1] + by};
            float2 v1 = {acc[mi][nt][2] + bx, acc[mi][nt][3] + by};
            stg_cs2(g_trans + (size_t)row0 * NN + col, v0);
            stg_cs2(g_trans + (size_t)(row0 + 8) * NN + col, v1);
        }
    }
}

// ---------------------------------------------------------------------------
// Scan step core (R8/R10 measured structure): double-buffered state; warps
// 12-15 compute state norm during matvec; 2 barriers/step; distance-1
// register prefetch. T loads use ld.global.cs (read-once streaming).
// ---------------------------------------------------------------------------
template <int T0, int T1>
__device__ __forceinline__ void scan_range(const float* __restrict__ Tb, int b,
                                           float* __restrict__ out,
                                           float (*s_nx)[DD], float (*red)[DD],
                                           float* wsum)
{
    const int tid = threadIdx.x;
    const int w = tid >> 5;
    const int l = tid & 31;
    const int c = w;                     // 8-row chunk
    const int j = l * 4;                 // 4-col group

    float4 cur[8];
#pragma unroll
    for (int ii = 0; ii < 8; ii++)
        cur[ii] = ldg_cs4(Tb + (size_t)T0 * NN + (size_t)(c * 8 + ii) * DD + j);
    __syncthreads();                     // BAR_A

#pragma unroll 1
    for (int t = T0; t < T1; t++) {
        const int rb = (t & 1) ^ 1;
        const int wb = t & 1;

        float4 nxt[8];
        if (t + 1 < T1) {
            const float* Tn = Tb + (size_t)(t + 1) * NN;
#pragma unroll
            for (int ii = 0; ii < 8; ii++)
                nxt[ii] = ldg_cs4(Tn + (size_t)(c * 8 + ii) * DD + j);
        }

        float4 p = {0.0f, 0.0f, 0.0f, 0.0f};
#pragma unroll
        for (int ii = 0; ii < 8; ii++) {
            float sv = s_nx[rb][c * 8 + ii];
            p.x = fmaf(sv, cur[ii].x, p.x);
            p.y = fmaf(sv, cur[ii].y, p.y);
            p.z = fmaf(sv, cur[ii].z, p.z);
            p.w = fmaf(sv, cur[ii].w, p.w);
        }
        *(float4*)&red[c][j] = p;

        if (w >= 12) {
            const int k = w - 12;
            float sv = s_nx[rb][k * 32 + l];
            float sq = sv * sv;
#pragma unroll
            for (int o = 16; o; o >>= 1) sq += __shfl_xor_sync(0xffffffffu, sq, o);
            if (l == 0) wsum[k] = sq;
        }
        __syncthreads();                 // BAR_B

        if (tid < DD) {
            float s0 = red[0][tid] + red[1][tid];
            float s1 = red[2][tid] + red[3][tid];
            float s2 = red[4][tid] + red[5][tid];
            float s3 = red[6][tid] + red[7][tid];
            float s4 = red[8][tid] + red[9][tid];
            float s5 = red[10][tid] + red[11][tid];
            float s6 = red[12][tid] + red[13][tid];
            float s7 = red[14][tid] + red[15][tid];
            float v = ((s0 + s1) + (s2 + s3)) + ((s4 + s5) + (s6 + s7));
            v = fmaxf(v, 0.0f);

            float inv = rsqrtf(fmaxf((wsum[0] + wsum[1]) + (wsum[2] + wsum[3]), 1e-24f));
            if (t > 0)
                out[((size_t)b * TT + (t - 1)) * DD + tid] = s_nx[rb][tid] * inv;
            s_nx[wb][tid] = v * inv;     // positive scale: exact (homogeneous)
        }
#pragma unroll
        for (int ii = 0; ii < 8; ii++) cur[ii] = nxt[ii];
        __syncthreads();                 // BAR_A (next step)
    }
}

#define TSPLIT 384

__global__ __launch_bounds__(512, 1) void scanA_kernel(const float* __restrict__ init_s,
                                                       float* __restrict__ out)
{
    __shared__ float s_nx[2][DD];
    __shared__ float red[16][DD];
    __shared__ float wsum[4];

    const int tid = threadIdx.x;
    const int b = blockIdx.x;
    const float* Tb = g_trans + (size_t)b * TT * (size_t)NN;

    if (tid < DD) s_nx[1][tid] = init_s[tid];   // rb of t=0

    scan_range<0, TSPLIT>(Tb, b, out, s_nx, red, wsum);

    if (tid < DD) g_state[b][tid] = s_nx[(TSPLIT - 1) & 1][tid];
}

__global__ __launch_bounds__(512, 1) void scanB_kernel(float* __restrict__ out)
{
    __shared__ float s_nx[2][DD];
    __shared__ float red[16][DD];
    __shared__ float wsum[4];

    const int tid = threadIdx.x;
    const int w = tid >> 5;
    const int l = tid & 31;
    const int b = blockIdx.x;
    const float* Tb = g_trans + (size_t)b * TT * (size_t)NN;

    if (tid < DD) s_nx[(TSPLIT & 1) ^ 1][tid] = g_state[b][tid];

    scan_range<TSPLIT, TT>(Tb, b, out, s_nx, red, wsum);

    const int fb = (TT - 1) & 1;
    if (w >= 12) {
        const int k = w - 12;
        float sv = s_nx[fb][k * 32 + l];
        float sq = sv * sv;
#pragma unroll
        for (int o = 16; o; o >>= 1) sq += __shfl_xor_sync(0xffffffffu, sq, o);
        if (l == 0) wsum[k] = sq;
    }
    __syncthreads();
    if (tid < DD) {
        float inv = rsqrtf(fmaxf((wsum[0] + wsum[1]) + (wsum[2] + wsum[3]), 1e-24f));
        out[((size_t)b * TT + (TT - 1)) * DD + tid] = s_nx[fb][tid] * inv;
    }
}

// ---------------------------------------------------------------------------
extern "C" void kernel_launch(void* const* d_in, const int* in_sizes, int n_in,
                              void* d_out, int out_size)
{
    const float* actions = (const float*)d_in[0];
    const float* init_s  = (const float*)d_in[1];
    const float* w1      = (const float*)d_in[2];
    const float* b1      = (const float*)d_in[3];
    const float* w2      = (const float*)d_in[4];
    const float* b2      = (const float*)d_in[5];
    float* out = (float*)d_out;

    static bool s_init = false;
    static cudaStream_t s2;
    static cudaEvent_t evF, evP, evA, evB, evJ;
    if (!s_init) {
        cudaStreamCreateWithFlags(&s2, cudaStreamNonBlocking);
        cudaEventCreateWithFlags(&evF, cudaEventDisableTiming);
        cudaEventCreateWithFlags(&evP, cudaEventDisableTiming);
        cudaEventCreateWithFlags(&evA, cudaEventDisableTiming);
        cudaEventCreateWithFlags(&evB, cudaEventDisableTiming);
        cudaEventCreateWithFlags(&evJ, cudaEventDisableTiming);
        s_init = true;
    }

    cudaFuncSetAttribute(gemm8_kernel, cudaFuncAttributeMaxDynamicSharedMemorySize,
                         NSTG * STAGE_BYTES);

    // Legal capture fork: record on origin stream FIRST, then s2 waits on it.
    cudaEventRecord(evF, 0);
    cudaStreamWaitEvent(s2, evF, 0);

    // mlp1 (stream 0) ∥ bprep (stream s2)
    mlp1_kernel<<<MM / 8, 256>>>(actions, w1, b1);
    bprep_kernel<<<dim3(NN / 32, KK / 32), dim3(32, 8), 0, s2>>>(w2);
    cudaEventRecord(evP, s2);
    cudaStreamWaitEvent(0, evP, 0);

    // gemmA: t-chunks 0..2 (y 0..95) — all batches, t in [0,384)
    gemm8_kernel<<<dim3(NN / BNG, 96), 256, NSTG * STAGE_BYTES>>>(b2, 0);
    cudaEventRecord(evA, 0);

    // scanA on s2, concurrent with gemmB
    cudaStreamWaitEvent(s2, evA, 0);
    scanA_kernel<<<BB, 512, 0, s2>>>(init_s, out);

    // gemmB: t-chunk 3 (y 96..127) — t in [384,512)
    gemm8_kernel<<<dim3(NN / BNG, 32), 256, NSTG * STAGE_BYTES>>>(b2, 96);
    cudaEventRecord(evB, 0);

    // scanB after gemmB (and after scanA by s2 stream order)
    cudaStreamWaitEvent(s2, evB, 0);
    scanB_kernel<<<BB, 512, 0, s2>>>(out);

    // join back to the main stream
    cudaEventRecord(evJ, s2);
    cudaStreamWaitEvent(0, evJ, 0);
}